// round 2
// baseline (speedup 1.0000x reference)
#include <cuda_runtime.h>
#include <cuda_bf16.h>

#define L 128
#define HALF 64

// One CTA per (b, i) pair. Thread (j, half) owns 64 k-elements of row j of
// s_pair[b,i,:,:] in registers; the 3 MFVI iterations run entirely from
// registers + a 128-float smem broadcast of sigmoid(q). s_pair (268 MB) is
// streamed from HBM exactly once (__ldcs), which is the roofline for this op.
//
// Mask is a bool tensor but the harness stores it in a 4-byte dtype (the
// harness dtype map has no bool); we read each element as a 32-bit word and
// test nonzero, which is correct for both int32 (1) and float32 (1.0f) forms.
__global__ __launch_bounds__(256, 2)
void mfvi_kernel(const float* __restrict__ s_span,
                 const float* __restrict__ s_pair,
                 const unsigned int* __restrict__ mask,
                 float* __restrict__ out)
{
    const int bi   = blockIdx.x;          // b*L + i
    const int i    = bi & (L - 1);
    const int tid  = threadIdx.x;
    const int j    = tid >> 1;            // row owned by this thread pair
    const int half = tid & 1;             // which 64-wide k-chunk
    const int kbase = half * HALF;

    const size_t row_off = ((size_t)bi * L + j) * L;
    const float4* sp4 = reinterpret_cast<const float4*>(s_pair + row_off + kbase);

    // Load this thread's 64 s_pair elements into registers (streaming hint:
    // zero reuse across threads/CTAs, keep it out of L2 residency).
    float a[HALF];
    #pragma unroll
    for (int u = 0; u < HALF / 4; ++u) {
        float4 v = __ldcs(sp4 + u);
        a[4*u+0] = v.x; a[4*u+1] = v.y; a[4*u+2] = v.z; a[4*u+3] = v.w;
    }

    // mask2o zeroes k==min(i,j) and k==max(i,j), i.e. k==i and k==j (once if
    // i==j). Compute the full dot product and subtract these terms, avoiding
    // dynamic-index register-array writes (which would force a spill).
    const float sp_ji = __ldg(s_pair + row_off + i);
    const float sp_jj = (i == j) ? 0.f : __ldg(s_pair + row_off + j);

    const float maskf = (mask[(size_t)bi * L + j] != 0u) ? 1.f : 0.f;
    const float sj    = s_span[(size_t)bi * L + j];

    __shared__ float sig[L];

    float q = sj;
    #pragma unroll
    for (int it = 0; it < 3; ++it) {
        if (half == 0) sig[j] = 1.f / (1.f + __expf(-q));
        __syncthreads();

        float sum = 0.f;
        const float4* sg4 = reinterpret_cast<const float4*>(sig + kbase);
        #pragma unroll
        for (int u = 0; u < HALF / 4; ++u) {
            float4 s4 = sg4[u];           // 2 distinct broadcast addrs/warp: conflict-free
            sum += a[4*u+0] * s4.x;
            sum += a[4*u+1] * s4.y;
            sum += a[4*u+2] * s4.z;
            sum += a[4*u+3] * s4.w;
        }
        // combine the two k-halves of row j
        sum += __shfl_xor_sync(0xffffffffu, sum, 1);
        // remove masked k==i / k==j contributions
        sum -= sp_ji * sig[i] + sp_jj * sig[j];
        q = sj + maskf * sum;
        __syncthreads();                  // readers done before sig is rewritten
    }

    if (half == 0)
        out[(size_t)bi * L + j] = 1.f / (1.f + __expf(-q));
}

extern "C" void kernel_launch(void* const* d_in, const int* in_sizes, int n_in,
                              void* d_out, int out_size) {
    const float*        s_span = (const float*)d_in[0];
    const float*        s_pair = (const float*)d_in[1];
    const unsigned int* mask   = (const unsigned int*)d_in[2];
    float*              out    = (float*)d_out;

    const int BL = in_sizes[0] / L;       // B * L CTAs (s_span has B*L*L elems)
    mfvi_kernel<<<BL, 256>>>(s_span, s_pair, mask, out);
}

// round 3
// speedup vs baseline: 1.8259x; 1.8259x over previous
#include <cuda_runtime.h>
#include <cuda_bf16.h>

#define L 128

__device__ __forceinline__ float sigmoidf(float x) {
    return 1.f / (1.f + __expf(-x));
}

// One CTA per (b,i). Warp w owns rows 16w..16w+15. TRANSPOSED register layout:
// lane l owns k in [4l, 4l+4) for all 16 rows of its warp, so each LDG.128
// reads one full row contiguously (4 L1 lines / 4 wavefronts — coalesced),
// and sigma needs only ONE conflict-free LDS.128 per lane per iteration.
// Row dot products are completed with a 5-stage multi-value shfl butterfly.
// The mask2o exclusions (k==i, k==row) are applied by zeroing a[] at load
// time with compile-time-indexed selects (no dynamic register indexing).
__global__ __launch_bounds__(256, 2)
void mfvi_kernel(const float* __restrict__ s_span,
                 const float* __restrict__ s_pair,
                 const unsigned int* __restrict__ mask,
                 float* __restrict__ out)
{
    const int bi  = blockIdx.x;            // b*L + i
    const int i   = bi & (L - 1);
    const int tid = threadIdx.x;
    const int w   = tid >> 5;              // warp id: rows 16w..16w+15
    const int l   = tid & 31;
    const int rg  = (w << 4) | (l & 15);   // row this lane finishes/owns

    const size_t base = (size_t)bi * L;
    const int k0 = 4 * l;                  // this lane's k range [k0, k0+4)

    // Load 16 rows x 4 k's into registers; stream (zero reuse) via __ldcs.
    float a[64];
    #pragma unroll
    for (int r = 0; r < 16; ++r) {
        const int row = (w << 4) + r;
        const float4* p4 =
            reinterpret_cast<const float4*>(s_pair + (base + row) * L) + l;
        float4 v = __ldcs(p4);
        // mask2o zeroes k==min(i,row) and k==max(i,row) == {i, row}
        a[4*r+0] = (k0+0 == i || k0+0 == row) ? 0.f : v.x;
        a[4*r+1] = (k0+1 == i || k0+1 == row) ? 0.f : v.y;
        a[4*r+2] = (k0+2 == i || k0+2 == row) ? 0.f : v.z;
        a[4*r+3] = (k0+3 == i || k0+3 == row) ? 0.f : v.w;
    }

    const float sj    = s_span[base + rg];
    const float maskf = (mask[base + rg] != 0u) ? 1.f : 0.f;

    __shared__ float sig[L];
    float q = sj;

    #pragma unroll
    for (int it = 0; it < 3; ++it) {
        if ((l & 16) == 0) sig[rg] = sigmoidf(q);
        __syncthreads();

        // One conflict-free LDS.128: lane l reads sig[4l..4l+3]
        float4 sg = *reinterpret_cast<const float4*>(sig + k0);

        // Per-lane partials for all 16 rows of this warp
        float p[16];
        #pragma unroll
        for (int r = 0; r < 16; ++r)
            p[r] = a[4*r+0]*sg.x + a[4*r+1]*sg.y
                 + a[4*r+2]*sg.z + a[4*r+3]*sg.w;

        // Multi-value butterfly: after stage s, p[t] = row (t<<(s+1) | l&mask)
        // summed over lanes differing in bits <= s. 8+4+2+1 = 15 shfl.
        #pragma unroll
        for (int s = 0; s < 4; ++s) {
            const int m  = 1 << s;
            const int my = (l >> s) & 1;
            #pragma unroll
            for (int t = 0; t < (8 >> s); ++t) {
                float keep = my ? p[2*t+1] : p[2*t];
                float give = my ? p[2*t]   : p[2*t+1];
                float recv = __shfl_xor_sync(0xffffffffu, give, m);
                p[t] = keep + recv;
            }
        }
        // Merge the two 16-lane halves: p[0] is row (l&15)'s half-sum
        float tot = p[0] + __shfl_xor_sync(0xffffffffu, p[0], 16);

        q = sj + maskf * tot;
        __syncthreads();   // all reads of sig done before next write
    }

    if ((l & 16) == 0)
        out[base + rg] = sigmoidf(q);
}

extern "C" void kernel_launch(void* const* d_in, const int* in_sizes, int n_in,
                              void* d_out, int out_size) {
    const float*        s_span = (const float*)d_in[0];
    const float*        s_pair = (const float*)d_in[1];
    const unsigned int* mask   = (const unsigned int*)d_in[2];
    float*              out    = (float*)d_out;

    const int BL = in_sizes[0] / L;   // B*L CTAs
    mfvi_kernel<<<BL, 256>>>(s_span, s_pair, mask, out);
}

// round 4
// speedup vs baseline: 1.8414x; 1.0085x over previous
#include <cuda_runtime.h>
#include <cuda_bf16.h>

#define L 128

__device__ __forceinline__ float sigmoidf(float x) {
    return 1.f / (1.f + __expf(-x));
}

// One CTA per (b,i), 512 threads. Warp w (0..15) owns rows 8w..8w+7; lane l
// owns k in [4l, 4l+4) for those 8 rows (32 data registers). Coalesced
// LDG.128 row loads (4 lines/instr), single conflict-free LDS.128 for sigma,
// 3-stage multi-value shfl butterfly + 2 cross-group shfl to finish row sums.
// mask2o exclusions (k==i, k==row) are folded into the load via
// compile-time-indexed selects. __launch_bounds__(512,2) caps regs at 64 so
// two CTAs (32 warps) fit per SM, doubling occupancy vs the 256-thread
// version to overlap load and compute phases across CTAs.
__global__ __launch_bounds__(512, 2)
void mfvi_kernel(const float* __restrict__ s_span,
                 const float* __restrict__ s_pair,
                 const unsigned int* __restrict__ mask,
                 float* __restrict__ out)
{
    const int bi  = blockIdx.x;            // b*L + i
    const int i   = bi & (L - 1);
    const int tid = threadIdx.x;
    const int w   = tid >> 5;              // warp id: rows 8w..8w+7
    const int l   = tid & 31;
    const int rg  = (w << 3) | (l & 7);    // row this lane finishes

    const size_t base = (size_t)bi * L;
    const int k0 = 4 * l;                  // this lane's k range [k0, k0+4)

    // Load 8 rows x 4 k's into registers; stream (zero reuse) via __ldcs.
    float a[32];
    #pragma unroll
    for (int r = 0; r < 8; ++r) {
        const int row = (w << 3) + r;
        const float4* p4 =
            reinterpret_cast<const float4*>(s_pair + (base + row) * L) + l;
        float4 v = __ldcs(p4);
        // mask2o zeroes k==min(i,row) and k==max(i,row) == {i, row}
        a[4*r+0] = (k0+0 == i || k0+0 == row) ? 0.f : v.x;
        a[4*r+1] = (k0+1 == i || k0+1 == row) ? 0.f : v.y;
        a[4*r+2] = (k0+2 == i || k0+2 == row) ? 0.f : v.z;
        a[4*r+3] = (k0+3 == i || k0+3 == row) ? 0.f : v.w;
    }

    const float sj    = s_span[base + rg];
    const float maskf = (mask[base + rg] != 0u) ? 1.f : 0.f;

    __shared__ float sig[L];
    float q = sj;

    #pragma unroll
    for (int it = 0; it < 3; ++it) {
        if (l < 8) sig[rg] = sigmoidf(q);
        __syncthreads();

        // One conflict-free LDS.128: lane l reads sig[4l..4l+3]
        float4 sg = *reinterpret_cast<const float4*>(sig + k0);

        // Per-lane partials for the 8 rows of this warp
        float p[8];
        #pragma unroll
        for (int r = 0; r < 8; ++r)
            p[r] = a[4*r+0]*sg.x + a[4*r+1]*sg.y
                 + a[4*r+2]*sg.z + a[4*r+3]*sg.w;

        // 3-stage multi-value butterfly over lane bits 0..2:
        // after stage s, p[t] = row (t<<(s+1) | l&((2<<s)-1)) partial.
        #pragma unroll
        for (int s = 0; s < 3; ++s) {
            const int m  = 1 << s;
            const int my = (l >> s) & 1;
            #pragma unroll
            for (int t = 0; t < (4 >> s); ++t) {
                float keep = my ? p[2*t+1] : p[2*t];
                float give = my ? p[2*t]   : p[2*t+1];
                float recv = __shfl_xor_sync(0xffffffffu, give, m);
                p[t] = keep + recv;
            }
        }
        // Combine the four 8-lane groups (distinct k-quarters of row l&7)
        float tot = p[0];
        tot += __shfl_xor_sync(0xffffffffu, tot, 8);
        tot += __shfl_xor_sync(0xffffffffu, tot, 16);

        q = sj + maskf * tot;
        __syncthreads();   // all reads of sig done before next write
    }

    if (l < 8)
        out[base + rg] = sigmoidf(q);
}

extern "C" void kernel_launch(void* const* d_in, const int* in_sizes, int n_in,
                              void* d_out, int out_size) {
    const float*        s_span = (const float*)d_in[0];
    const float*        s_pair = (const float*)d_in[1];
    const unsigned int* mask   = (const unsigned int*)d_in[2];
    float*              out    = (float*)d_out;

    const int BL = in_sizes[0] / L;   // B*L CTAs
    mfvi_kernel<<<BL, 512>>>(s_span, s_pair, mask, out);
}